// round 6
// baseline (speedup 1.0000x reference)
#include <cuda_runtime.h>

#define NPTS 512
#define CDIM 384
#define LDIM 208   // 192 QK + 16 pair
#define NB 8

// ---------------- device scratch ----------------
__device__ float g_L[NB * NPTS * LDIM];  // [Q*HEAD_SCALE | ap*relu(x@Wpi+bpi)]
__device__ float g_R[NB * NPTS * LDIM];  // [K            | relu(x@Wpj+bpj)   ]
__device__ float g_d[NB * NPTS];         // x@Wd + bd
__device__ float g_rot[2 * NB];          // (cos t0, sin t0) per batch

// ---------------- threefry / jax normal ----------------
__device__ __forceinline__ unsigned rotl32(unsigned v, int s) {
    return (v << s) | (v >> (32 - s));
}

__device__ void threefry2x32(unsigned k0, unsigned k1, unsigned c0, unsigned c1,
                             unsigned& o0, unsigned& o1) {
    unsigned k2 = k0 ^ k1 ^ 0x1BD11BDAu;
    unsigned x0 = c0 + k0, x1 = c1 + k1;
#define TF_R(r) { x0 += x1; x1 = rotl32(x1, r); x1 ^= x0; }
    TF_R(13) TF_R(15) TF_R(26) TF_R(6)   x0 += k1; x1 += k2 + 1u;
    TF_R(17) TF_R(29) TF_R(16) TF_R(24)  x0 += k2; x1 += k0 + 2u;
    TF_R(13) TF_R(15) TF_R(26) TF_R(6)   x0 += k0; x1 += k1 + 3u;
    TF_R(17) TF_R(29) TF_R(16) TF_R(24)  x0 += k1; x1 += k2 + 4u;
    TF_R(13) TF_R(15) TF_R(26) TF_R(6)   x0 += k2; x1 += k0 + 5u;
#undef TF_R
    o0 = x0; o1 = x1;
}

// jax partitionable threefry random bits (jax/_src/prng.py):
//   counts1, counts2 = iota_2x32_shape(shape)   -> (0, i) for i < 2^32
//   bits1, bits2 = threefry2x32(key, counts)
//   bit_width 32: return bits1 ^ bits2
__device__ unsigned jax_random_bits_partitionable(unsigned i) {
    unsigned o0, o1;
    threefry2x32(0u, 42u, 0u, i, o0, o1);
    return o0 ^ o1;
}

__device__ float erfinv_f(float x) {
    float w = -log1pf(-x * x);
    float p;
    if (w < 5.0f) {
        w -= 2.5f;
        p = 2.81022636e-08f;
        p = fmaf(p, w, 3.43273939e-07f);
        p = fmaf(p, w, -3.5233877e-06f);
        p = fmaf(p, w, -4.39150654e-06f);
        p = fmaf(p, w, 0.00021858087f);
        p = fmaf(p, w, -0.00125372503f);
        p = fmaf(p, w, -0.00417768164f);
        p = fmaf(p, w, 0.246640727f);
        p = fmaf(p, w, 1.50140941f);
    } else {
        w = sqrtf(w) - 3.0f;
        p = -0.000200214257f;
        p = fmaf(p, w, 0.000100950558f);
        p = fmaf(p, w, 0.00134934322f);
        p = fmaf(p, w, -0.00367342844f);
        p = fmaf(p, w, 0.00573950773f);
        p = fmaf(p, w, -0.0076224613f);
        p = fmaf(p, w, 0.00943887047f);
        p = fmaf(p, w, 1.00167406f);
        p = fmaf(p, w, 2.83297682f);
    }
    return p * x;
}

__device__ float jax_normal_from_bits(unsigned bits) {
    float f = __uint_as_float((bits >> 9) | 0x3f800000u) - 1.0f;  // [0,1)
    float lo = __uint_as_float(0xBF7FFFFFu);                      // nextafter(-1,0)
    float span = 1.0f - lo;
    float val = f * span + lo;
    val = fmaxf(lo, val);
    return 1.41421356237f * erfinv_f(val);
}

// ---------------- theta0: covariance + power iteration ----------------
__global__ void theta0_kernel(const float* __restrict__ xy) {
    int w = threadIdx.x >> 5, lane = threadIdx.x & 31;
    const float* p = xy + (size_t)w * NPTS * 2;
    float sx = 0.f, sy = 0.f;
    for (int i = lane; i < NPTS; i += 32) { sx += p[2 * i]; sy += p[2 * i + 1]; }
    for (int o = 16; o; o >>= 1) {
        sx += __shfl_xor_sync(~0u, sx, o);
        sy += __shfl_xor_sync(~0u, sy, o);
    }
    float mx = sx / (float)NPTS, my = sy / (float)NPTS;
    float cxx = 0.f, cxy = 0.f, cyy = 0.f;
    for (int i = lane; i < NPTS; i += 32) {
        float a = p[2 * i] - mx, b = p[2 * i + 1] - my;
        cxx += a * a; cxy += a * b; cyy += b * b;
    }
    for (int o = 16; o; o >>= 1) {
        cxx += __shfl_xor_sync(~0u, cxx, o);
        cxy += __shfl_xor_sync(~0u, cxy, o);
        cyy += __shfl_xor_sync(~0u, cyy, o);
    }
    if (lane == 0) {
        float denom = (float)NPTS + 1e-8f;
        cxx /= denom; cxy /= denom; cyy /= denom;
        // v flat index: element (b, d, 0) = flat[2b + d]
        unsigned n0bits = jax_random_bits_partitionable(2u * (unsigned)w);
        unsigned n1bits = jax_random_bits_partitionable(2u * (unsigned)w + 1u);
        float v0 = jax_normal_from_bits(n0bits);
        float v1 = jax_normal_from_bits(n1bits);
        float nrm = sqrtf(v0 * v0 + v1 * v1);
        v0 /= (nrm + 1e-8f); v1 /= (nrm + 1e-8f);
#pragma unroll
        for (int it = 0; it < 5; ++it) {
            float w0 = cxx * v0 + cxy * v1;
            float w1 = cxy * v0 + cyy * v1;
            nrm = sqrtf(w0 * w0 + w1 * w1);
            v0 = w0 / (nrm + 1e-8f);
            v1 = w1 / (nrm + 1e-8f);
        }
        g_rot[2 * w] = v0;      // cos theta0
        g_rot[2 * w + 1] = v1;  // sin theta0
    }
}

// ---------------- fused fold + projection GEMM ----------------
// out columns j: [0,192) Q*HS -> L   [192,384) K -> R
//                [384,400) ap*relu(.+bpi) -> L[192..]   [400,416) relu(.+bpj) -> R[192..]
//                416: x@Wd+bd -> g_d
__global__ __launch_bounds__(256) void proj_gemm_kernel(
    const float* __restrict__ feats,
    const float* __restrict__ Wq, const float* __restrict__ Wk,
    const float* __restrict__ Wpi, const float* __restrict__ bpi,
    const float* __restrict__ Wpj, const float* __restrict__ bpj,
    const float* __restrict__ alpha_pair,
    const float* __restrict__ Wd, const float* __restrict__ bd) {
    __shared__ float As[16][128];
    __shared__ float Bs[16][64];
    int tid = threadIdx.x;
    int n0 = blockIdx.x * 64;
    int m0 = blockIdx.y * 128;
    int tr = tid >> 4, tc = tid & 15;
    float acc[8][4];
#pragma unroll
    for (int i = 0; i < 8; i++)
#pragma unroll
        for (int j = 0; j < 4; j++) acc[i][j] = 0.f;

    for (int kc = 0; kc < CDIM; kc += 16) {
#pragma unroll
        for (int it = 0; it < 2; ++it) {
            int id = tid + it * 256;
            int row = id >> 2, q = id & 3;
            int pidx = m0 + row;
            int b = pidx >> 9, n = pidx & 511;
            const float* base = feats + ((size_t)b * (2 * NPTS + 1) + 1 + 2 * n) * CDIM + kc + q * 4;
            float4 u = *(const float4*)base;
            float4 v = *(const float4*)(base + CDIM);
            As[q * 4 + 0][row] = 0.5f * (u.x + v.x);
            As[q * 4 + 1][row] = 0.5f * (u.y + v.y);
            As[q * 4 + 2][row] = 0.5f * (u.z + v.z);
            As[q * 4 + 3][row] = 0.5f * (u.w + v.w);
        }
#pragma unroll
        for (int it = 0; it < 4; ++it) {
            int id = tid + it * 256;
            int k = id >> 6, n = id & 63;
            int j = n0 + n;
            int kk = kc + k;
            float w;
            if (j < 192)      w = Wq[kk * 192 + j];
            else if (j < 384) w = Wk[kk * 192 + j - 192];
            else if (j < 400) w = Wpi[kk * 16 + j - 384];
            else if (j < 416) w = Wpj[kk * 16 + j - 400];
            else if (j == 416) w = Wd[kk];
            else              w = 0.f;
            Bs[k][n] = w;
        }
        __syncthreads();
#pragma unroll
        for (int k = 0; k < 16; ++k) {
            float a[8], bb[4];
            float4 a0 = *(const float4*)&As[k][tr * 8];
            float4 a1 = *(const float4*)&As[k][tr * 8 + 4];
            a[0] = a0.x; a[1] = a0.y; a[2] = a0.z; a[3] = a0.w;
            a[4] = a1.x; a[5] = a1.y; a[6] = a1.z; a[7] = a1.w;
            float4 b4 = *(const float4*)&Bs[k][tc * 4];
            bb[0] = b4.x; bb[1] = b4.y; bb[2] = b4.z; bb[3] = b4.w;
#pragma unroll
            for (int i = 0; i < 8; i++)
#pragma unroll
                for (int j = 0; j < 4; j++)
                    acc[i][j] = fmaf(a[i], bb[j], acc[i][j]);
        }
        __syncthreads();
    }

    float ap = fmaxf(alpha_pair[0], 0.f);
    float bd0 = bd[0];
    const float HS = 0.17677669529663687f;  // 1/sqrt(32)
#pragma unroll
    for (int jj = 0; jj < 4; ++jj) {
        int j = n0 + tc * 4 + jj;
        if (j > 416) continue;
#pragma unroll
        for (int ii = 0; ii < 8; ++ii) {
            int p = m0 + tr * 8 + ii;
            float v = acc[ii][jj];
            if (j < 192)       g_L[(size_t)p * LDIM + j] = v * HS;
            else if (j < 384)  g_R[(size_t)p * LDIM + (j - 192)] = v;
            else if (j < 400)  g_L[(size_t)p * LDIM + 192 + (j - 384)] = fmaxf(v + bpi[j - 384], 0.f) * ap;
            else if (j < 416)  g_R[(size_t)p * LDIM + 192 + (j - 400)] = fmaxf(v + bpj[j - 400], 0.f);
            else               g_d[p] = v + bd0;
        }
    }
}

// ---------------- batched S0 = L * R^T ----------------
__global__ __launch_bounds__(256) void qk_gemm_kernel(float* __restrict__ S) {
    __shared__ float Ls[16][128];
    __shared__ float Rs[16][128];
    int tid = threadIdx.x;
    int b = blockIdx.z;
    int m0 = blockIdx.x * 128;
    int n0 = blockIdx.y * 128;
    int tr = tid >> 4, tc = tid & 15;
    float acc[8][8];
#pragma unroll
    for (int i = 0; i < 8; i++)
#pragma unroll
        for (int j = 0; j < 8; j++) acc[i][j] = 0.f;

    const float* Lb = g_L + (size_t)b * NPTS * LDIM;
    const float* Rb = g_R + (size_t)b * NPTS * LDIM;

    for (int kc = 0; kc < LDIM; kc += 16) {
#pragma unroll
        for (int it = 0; it < 2; ++it) {
            int id = tid + it * 256;
            int row = id >> 2, q = id & 3;
            float4 u = *(const float4*)&Lb[(size_t)(n0 + row) * LDIM + kc + q * 4];
            Ls[q * 4 + 0][row] = u.x; Ls[q * 4 + 1][row] = u.y;
            Ls[q * 4 + 2][row] = u.z; Ls[q * 4 + 3][row] = u.w;
            float4 v = *(const float4*)&Rb[(size_t)(m0 + row) * LDIM + kc + q * 4];
            Rs[q * 4 + 0][row] = v.x; Rs[q * 4 + 1][row] = v.y;
            Rs[q * 4 + 2][row] = v.z; Rs[q * 4 + 3][row] = v.w;
        }
        __syncthreads();
#pragma unroll
        for (int k = 0; k < 16; ++k) {
            float a[8], bb[8];
            float4 a0 = *(const float4*)&Ls[k][tr * 8];
            float4 a1 = *(const float4*)&Ls[k][tr * 8 + 4];
            a[0] = a0.x; a[1] = a0.y; a[2] = a0.z; a[3] = a0.w;
            a[4] = a1.x; a[5] = a1.y; a[6] = a1.z; a[7] = a1.w;
            float4 b0 = *(const float4*)&Rs[k][tc * 8];
            float4 b1 = *(const float4*)&Rs[k][tc * 8 + 4];
            bb[0] = b0.x; bb[1] = b0.y; bb[2] = b0.z; bb[3] = b0.w;
            bb[4] = b1.x; bb[5] = b1.y; bb[6] = b1.z; bb[7] = b1.w;
#pragma unroll
            for (int i = 0; i < 8; i++)
#pragma unroll
                for (int j = 0; j < 8; j++)
                    acc[i][j] = fmaf(a[i], bb[j], acc[i][j]);
        }
        __syncthreads();
    }
#pragma unroll
    for (int i = 0; i < 8; i++) {
        size_t off = ((size_t)b * NPTS + n0 + tr * 8 + i) * NPTS + m0 + tc * 8;
        *(float4*)&S[off] = make_float4(acc[i][0], acc[i][1], acc[i][2], acc[i][3]);
        *(float4*)&S[off + 4] = make_float4(acc[i][4], acc[i][5], acc[i][6], acc[i][7]);
    }
}

// ---------------- per-pair geometry/angle MLP epilogue ----------------
__global__ __launch_bounds__(256) void pair_kernel(
    float* __restrict__ S, const float* __restrict__ xy,
    const float* __restrict__ Wg1, const float* __restrict__ bg1,
    const float* __restrict__ Wg2, const float* __restrict__ bg2,
    const float* __restrict__ alpha_geom,
    const float* __restrict__ Wa1, const float* __restrict__ ba1,
    const float* __restrict__ Wa2, const float* __restrict__ ba2,
    const float* __restrict__ alpha_angle,
    const float* __restrict__ logit_scale) {
    __shared__ float sWg1[12 * 32];
    __shared__ float sbg1[32];
    __shared__ float sWg2[32];
    __shared__ float sWa1[6 * 16];
    __shared__ float sba1[16];
    __shared__ float sWa2[16];
    __shared__ float sxn[32], syn[32], sxm[32], sym[32], sdn[32];

    int tid = threadIdx.x;
    int b = blockIdx.z;
    int m0 = blockIdx.x * 32;
    int n0 = blockIdx.y * 32;

    for (int i = tid; i < 384; i += 256) sWg1[i] = Wg1[i];
    if (tid < 96) sWa1[tid] = Wa1[tid];
    if (tid >= 96 && tid < 128) { sbg1[tid - 96] = bg1[tid - 96]; sWg2[tid - 96] = Wg2[tid - 96]; }
    if (tid >= 128 && tid < 144) { sba1[tid - 128] = ba1[tid - 128]; sWa2[tid - 128] = Wa2[tid - 128]; }
    if (tid >= 160 && tid < 192) {
        int i = tid - 160;
        float2 pn = *(const float2*)&xy[((size_t)b * NPTS + n0 + i) * 2];
        syn[i] = pn.x; sxn[i] = pn.y;   // xy[...,0] = yv, xy[...,1] = xv
        float2 pm = *(const float2*)&xy[((size_t)b * NPTS + m0 + i) * 2];
        sym[i] = pm.x; sxm[i] = pm.y;
        sdn[i] = g_d[b * NPTS + n0 + i];
    }
    __syncthreads();

    int ty = tid >> 3;      // 0..31 : n within tile
    int tx = tid & 7;       // 0..7  : group of 4 m
    int n = n0 + ty;
    int mbase = m0 + tx * 4;

    float c0 = g_rot[2 * b], s0 = g_rot[2 * b + 1];
    float yn = syn[ty], xn = sxn[ty];

    const float sp = 1.41421356237f / 7.0f;                 // rbf spacing
    const float gam = 1.0f / (2.0f * sp * sp + 1e-8f);

    float f[4][12];
#pragma unroll
    for (int p = 0; p < 4; ++p) {
        float ym = sym[tx * 4 + p], xm = sxm[tx * 4 + p];
        float dy = yn - ym, dx = xn - xm;
        float r2 = dy * dy + dx * dx;
        float r = sqrtf(r2 + 1e-8f);
        float inv = rsqrtf(r2);
        float ct, st;
        if (r2 == 0.f) { ct = 1.f; st = 0.f; }
        else { ct = dx * inv; st = dy * inv; }
        float c1 = ct * c0 + st * s0;   // cos(theta - theta0)
        float s1 = st * c0 - ct * s0;   // sin(theta - theta0)
        f[p][0] = dy; f[p][1] = dx;
#pragma unroll
        for (int k = 0; k < 8; ++k) {
            float dmu = r - (float)k * sp;
            f[p][2 + k] = __expf(-gam * dmu * dmu);
        }
        f[p][10] = c1; f[p][11] = s1;
    }

    float bg2v = bg2[0], ba2v = ba2[0];
    float accG[4] = {bg2v, bg2v, bg2v, bg2v};
    float accA[4] = {ba2v, ba2v, ba2v, ba2v};

#pragma unroll 4
    for (int j = 0; j < 32; ++j) {
        float w2 = sWg2[j];
        float bj = sbg1[j];
        float h0 = bj, h1 = bj, h2 = bj, h3 = bj;
#pragma unroll
        for (int i = 0; i < 12; ++i) {
            float w = sWg1[i * 32 + j];
            h0 = fmaf(f[0][i], w, h0);
            h1 = fmaf(f[1][i], w, h1);
            h2 = fmaf(f[2][i], w, h2);
            h3 = fmaf(f[3][i], w, h3);
        }
        accG[0] = fmaf(fmaxf(h0, 0.f), w2, accG[0]);
        accG[1] = fmaf(fmaxf(h1, 0.f), w2, accG[1]);
        accG[2] = fmaf(fmaxf(h2, 0.f), w2, accG[2]);
        accG[3] = fmaf(fmaxf(h3, 0.f), w2, accG[3]);
    }

    // reuse f[p][0..5] for angle features
#pragma unroll
    for (int p = 0; p < 4; ++p) {
        float c1 = f[p][10], s1 = f[p][11];
        float c2 = c1 * c1 - s1 * s1;
        float s2 = 2.f * c1 * s1;
        float c4 = c2 * c2 - s2 * s2;
        float s4 = 2.f * c2 * s2;
        f[p][0] = c1; f[p][1] = s1; f[p][2] = c2;
        f[p][3] = s2; f[p][4] = c4; f[p][5] = s4;
    }

#pragma unroll 4
    for (int j = 0; j < 16; ++j) {
        float w2 = sWa2[j];
        float bj = sba1[j];
        float h0 = bj, h1 = bj, h2 = bj, h3 = bj;
#pragma unroll
        for (int i = 0; i < 6; ++i) {
            float w = sWa1[i * 16 + j];
            h0 = fmaf(f[0][i], w, h0);
            h1 = fmaf(f[1][i], w, h1);
            h2 = fmaf(f[2][i], w, h2);
            h3 = fmaf(f[3][i], w, h3);
        }
        accA[0] = fmaf(fmaxf(h0, 0.f), w2, accA[0]);
        accA[1] = fmaf(fmaxf(h1, 0.f), w2, accA[1]);
        accA[2] = fmaf(fmaxf(h2, 0.f), w2, accA[2]);
        accA[3] = fmaf(fmaxf(h3, 0.f), w2, accA[3]);
    }

    float ag = fmaxf(alpha_geom[0], 0.f);
    float aa = fmaxf(alpha_angle[0], 0.f);
    float ls = fmaxf(logit_scale[0], 0.01f);

    size_t off = ((size_t)b * NPTS + n) * NPTS + mbase;
    float4 s4v = *(const float4*)&S[off];
    float sv[4] = {s4v.x, s4v.y, s4v.z, s4v.w};
#pragma unroll
    for (int p = 0; p < 4; ++p) {
        float v = sv[p] + ag * accG[p] + aa * accA[p];
        if (n == mbase + p) v += sdn[ty];
        sv[p] = v * ls;
    }
    *(float4*)&S[off] = make_float4(sv[0], sv[1], sv[2], sv[3]);
}

// ---------------- launch ----------------
extern "C" void kernel_launch(void* const* d_in, const int* in_sizes, int n_in,
                              void* d_out, int out_size) {
    const float* feats       = (const float*)d_in[0];
    const float* xy          = (const float*)d_in[1];
    const float* Wq          = (const float*)d_in[2];
    const float* Wk          = (const float*)d_in[3];
    const float* Wpi         = (const float*)d_in[4];
    const float* bpi         = (const float*)d_in[5];
    const float* Wpj         = (const float*)d_in[6];
    const float* bpj         = (const float*)d_in[7];
    const float* alpha_pair  = (const float*)d_in[8];
    const float* Wg1         = (const float*)d_in[9];
    const float* bg1         = (const float*)d_in[10];
    const float* Wg2         = (const float*)d_in[11];
    const float* bg2         = (const float*)d_in[12];
    const float* alpha_geom  = (const float*)d_in[13];
    const float* Wa1         = (const float*)d_in[14];
    const float* ba1         = (const float*)d_in[15];
    const float* Wa2         = (const float*)d_in[16];
    const float* ba2         = (const float*)d_in[17];
    const float* alpha_angle = (const float*)d_in[18];
    const float* Wd          = (const float*)d_in[19];
    const float* bd          = (const float*)d_in[20];
    const float* logit_scale = (const float*)d_in[21];
    float* S = (float*)d_out;

    theta0_kernel<<<1, 256>>>(xy);
    proj_gemm_kernel<<<dim3(7, 32), 256>>>(feats, Wq, Wk, Wpi, bpi, Wpj, bpj,
                                           alpha_pair, Wd, bd);
    qk_gemm_kernel<<<dim3(4, 4, 8), 256>>>(S);
    pair_kernel<<<dim3(16, 16, 8), 256>>>(S, xy, Wg1, bg1, Wg2, bg2, alpha_geom,
                                          Wa1, ba1, Wa2, ba2, alpha_angle,
                                          logit_scale);
}

// round 7
// speedup vs baseline: 1.1051x; 1.1051x over previous
#include <cuda_runtime.h>

#define NPTS 512
#define CDIM 384
#define LDIM 208   // 192 QK + 16 pair
#define NB 8
#define WCOLS 417  // packed projection columns

typedef unsigned long long ull;

// ---------------- device scratch ----------------
__device__ float g_L[NB * NPTS * LDIM];  // [Q*HEAD_SCALE | ap*relu(x@Wpi+bpi)]
__device__ float g_R[NB * NPTS * LDIM];  // [K            | relu(x@Wpj+bpj)   ]
__device__ float g_d[NB * NPTS];         // x@Wd + bd
__device__ float g_rot[2 * NB];          // (cos t0, sin t0) per batch
__device__ float g_W[CDIM * WCOLS];      // packed [Wq|Wk|Wpi|Wpj|Wd]

// ---------------- f32x2 helpers ----------------
__device__ __forceinline__ ull pack2(float lo, float hi) {
    ull r; asm("mov.b64 %0,{%1,%2};" : "=l"(r) : "f"(lo), "f"(hi)); return r;
}
__device__ __forceinline__ void unpack2(ull v, float& lo, float& hi) {
    asm("mov.b64 {%0,%1},%2;" : "=f"(lo), "=f"(hi) : "l"(v));
}
__device__ __forceinline__ ull fma2(ull a, ull b, ull c) {
    ull d; asm("fma.rn.f32x2 %0,%1,%2,%3;" : "=l"(d) : "l"(a), "l"(b), "l"(c)); return d;
}

// ---------------- threefry / jax normal ----------------
__device__ __forceinline__ unsigned rotl32(unsigned v, int s) {
    return (v << s) | (v >> (32 - s));
}

__device__ void threefry2x32(unsigned k0, unsigned k1, unsigned c0, unsigned c1,
                             unsigned& o0, unsigned& o1) {
    unsigned k2 = k0 ^ k1 ^ 0x1BD11BDAu;
    unsigned x0 = c0 + k0, x1 = c1 + k1;
#define TF_R(r) { x0 += x1; x1 = rotl32(x1, r); x1 ^= x0; }
    TF_R(13) TF_R(15) TF_R(26) TF_R(6)   x0 += k1; x1 += k2 + 1u;
    TF_R(17) TF_R(29) TF_R(16) TF_R(24)  x0 += k2; x1 += k0 + 2u;
    TF_R(13) TF_R(15) TF_R(26) TF_R(6)   x0 += k0; x1 += k1 + 3u;
    TF_R(17) TF_R(29) TF_R(16) TF_R(24)  x0 += k1; x1 += k2 + 4u;
    TF_R(13) TF_R(15) TF_R(26) TF_R(6)   x0 += k2; x1 += k0 + 5u;
#undef TF_R
    o0 = x0; o1 = x1;
}

// jax partitionable threefry random bits: bits[i] = o0 ^ o1 of tf2x32(key,(0,i))
__device__ unsigned jax_random_bits_partitionable(unsigned i) {
    unsigned o0, o1;
    threefry2x32(0u, 42u, 0u, i, o0, o1);
    return o0 ^ o1;
}

__device__ float erfinv_f(float x) {
    float w = -log1pf(-x * x);
    float p;
    if (w < 5.0f) {
        w -= 2.5f;
        p = 2.81022636e-08f;
        p = fmaf(p, w, 3.43273939e-07f);
        p = fmaf(p, w, -3.5233877e-06f);
        p = fmaf(p, w, -4.39150654e-06f);
        p = fmaf(p, w, 0.00021858087f);
        p = fmaf(p, w, -0.00125372503f);
        p = fmaf(p, w, -0.00417768164f);
        p = fmaf(p, w, 0.246640727f);
        p = fmaf(p, w, 1.50140941f);
    } else {
        w = sqrtf(w) - 3.0f;
        p = -0.000200214257f;
        p = fmaf(p, w, 0.000100950558f);
        p = fmaf(p, w, 0.00134934322f);
        p = fmaf(p, w, -0.00367342844f);
        p = fmaf(p, w, 0.00573950773f);
        p = fmaf(p, w, -0.0076224613f);
        p = fmaf(p, w, 0.00943887047f);
        p = fmaf(p, w, 1.00167406f);
        p = fmaf(p, w, 2.83297682f);
    }
    return p * x;
}

__device__ float jax_normal_from_bits(unsigned bits) {
    float f = __uint_as_float((bits >> 9) | 0x3f800000u) - 1.0f;  // [0,1)
    float lo = __uint_as_float(0xBF7FFFFFu);                      // nextafter(-1,0)
    float span = 1.0f - lo;
    float val = f * span + lo;
    val = fmaxf(lo, val);
    return 1.41421356237f * erfinv_f(val);
}

// ---------------- theta0: covariance + power iteration ----------------
__global__ void theta0_kernel(const float* __restrict__ xy) {
    int w = threadIdx.x >> 5, lane = threadIdx.x & 31;
    const float* p = xy + (size_t)w * NPTS * 2;
    float sx = 0.f, sy = 0.f;
    for (int i = lane; i < NPTS; i += 32) { sx += p[2 * i]; sy += p[2 * i + 1]; }
    for (int o = 16; o; o >>= 1) {
        sx += __shfl_xor_sync(~0u, sx, o);
        sy += __shfl_xor_sync(~0u, sy, o);
    }
    float mx = sx / (float)NPTS, my = sy / (float)NPTS;
    float cxx = 0.f, cxy = 0.f, cyy = 0.f;
    for (int i = lane; i < NPTS; i += 32) {
        float a = p[2 * i] - mx, b = p[2 * i + 1] - my;
        cxx += a * a; cxy += a * b; cyy += b * b;
    }
    for (int o = 16; o; o >>= 1) {
        cxx += __shfl_xor_sync(~0u, cxx, o);
        cxy += __shfl_xor_sync(~0u, cxy, o);
        cyy += __shfl_xor_sync(~0u, cyy, o);
    }
    if (lane == 0) {
        float denom = (float)NPTS + 1e-8f;
        cxx /= denom; cxy /= denom; cyy /= denom;
        unsigned n0bits = jax_random_bits_partitionable(2u * (unsigned)w);
        unsigned n1bits = jax_random_bits_partitionable(2u * (unsigned)w + 1u);
        float v0 = jax_normal_from_bits(n0bits);
        float v1 = jax_normal_from_bits(n1bits);
        float nrm = sqrtf(v0 * v0 + v1 * v1);
        v0 /= (nrm + 1e-8f); v1 /= (nrm + 1e-8f);
#pragma unroll
        for (int it = 0; it < 5; ++it) {
            float w0 = cxx * v0 + cxy * v1;
            float w1 = cxy * v0 + cyy * v1;
            nrm = sqrtf(w0 * w0 + w1 * w1);
            v0 = w0 / (nrm + 1e-8f);
            v1 = w1 / (nrm + 1e-8f);
        }
        g_rot[2 * w] = v0;      // cos theta0
        g_rot[2 * w + 1] = v1;  // sin theta0
    }
}

// ---------------- pack projection weights into one matrix ----------------
__global__ void pack_w_kernel(const float* __restrict__ Wq, const float* __restrict__ Wk,
                              const float* __restrict__ Wpi, const float* __restrict__ Wpj,
                              const float* __restrict__ Wd) {
    int idx = blockIdx.x * 256 + threadIdx.x;
    if (idx >= CDIM * WCOLS) return;
    int k = idx / WCOLS, j = idx - k * WCOLS;
    float w;
    if (j < 192)       w = Wq[k * 192 + j];
    else if (j < 384)  w = Wk[k * 192 + j - 192];
    else if (j < 400)  w = Wpi[k * 16 + j - 384];
    else if (j < 416)  w = Wpj[k * 16 + j - 400];
    else               w = Wd[k];
    g_W[idx] = w;
}

// ---------------- fused fold + projection GEMM (f32x2) ----------------
__global__ __launch_bounds__(256) void proj_gemm_kernel(
    const float* __restrict__ feats,
    const float* __restrict__ bpi, const float* __restrict__ bpj,
    const float* __restrict__ alpha_pair, const float* __restrict__ bd) {
    __shared__ float As[16][128];
    __shared__ float Bs[16][64];
    int tid = threadIdx.x;
    int n0 = blockIdx.x * 64;
    int m0 = blockIdx.y * 128;
    int tr = tid >> 4, tc = tid & 15;
    ull acc2[4][4];
#pragma unroll
    for (int i = 0; i < 4; i++)
#pragma unroll
        for (int j = 0; j < 4; j++) acc2[i][j] = 0ull;

    for (int kc = 0; kc < CDIM; kc += 16) {
#pragma unroll
        for (int it = 0; it < 2; ++it) {
            int id = tid + it * 256;
            int row = id >> 2, q = id & 3;
            int pidx = m0 + row;
            int b = pidx >> 9, n = pidx & 511;
            const float* base = feats + ((size_t)b * (2 * NPTS + 1) + 1 + 2 * n) * CDIM + kc + q * 4;
            float4 u = *(const float4*)base;
            float4 v = *(const float4*)(base + CDIM);
            As[q * 4 + 0][row] = 0.5f * (u.x + v.x);
            As[q * 4 + 1][row] = 0.5f * (u.y + v.y);
            As[q * 4 + 2][row] = 0.5f * (u.z + v.z);
            As[q * 4 + 3][row] = 0.5f * (u.w + v.w);
        }
#pragma unroll
        for (int it = 0; it < 4; ++it) {
            int id = tid + it * 256;
            int k = id >> 6, n = id & 63;
            int j = n0 + n;
            Bs[k][n] = (j < WCOLS) ? g_W[(size_t)(kc + k) * WCOLS + j] : 0.f;
        }
        __syncthreads();
#pragma unroll
        for (int k = 0; k < 16; ++k) {
            float4 a0 = *(const float4*)&As[k][tr * 8];
            float4 a1 = *(const float4*)&As[k][tr * 8 + 4];
            ull a2[4] = {pack2(a0.x, a0.y), pack2(a0.z, a0.w),
                         pack2(a1.x, a1.y), pack2(a1.z, a1.w)};
            float4 b4 = *(const float4*)&Bs[k][tc * 4];
            ull bd2[4] = {pack2(b4.x, b4.x), pack2(b4.y, b4.y),
                          pack2(b4.z, b4.z), pack2(b4.w, b4.w)};
#pragma unroll
            for (int i = 0; i < 4; i++)
#pragma unroll
                for (int j = 0; j < 4; j++)
                    acc2[i][j] = fma2(a2[i], bd2[j], acc2[i][j]);
        }
        __syncthreads();
    }

    float acc[8][4];
#pragma unroll
    for (int i = 0; i < 4; i++)
#pragma unroll
        for (int j = 0; j < 4; j++)
            unpack2(acc2[i][j], acc[2 * i][j], acc[2 * i + 1][j]);

    float ap = fmaxf(alpha_pair[0], 0.f);
    float bd0 = bd[0];
    const float HS = 0.17677669529663687f;  // 1/sqrt(32)
#pragma unroll
    for (int jj = 0; jj < 4; ++jj) {
        int j = n0 + tc * 4 + jj;
        if (j > 416) continue;
#pragma unroll
        for (int ii = 0; ii < 8; ++ii) {
            int p = m0 + tr * 8 + ii;
            float v = acc[ii][jj];
            if (j < 192)       g_L[(size_t)p * LDIM + j] = v * HS;
            else if (j < 384)  g_R[(size_t)p * LDIM + (j - 192)] = v;
            else if (j < 400)  g_L[(size_t)p * LDIM + 192 + (j - 384)] = fmaxf(v + bpi[j - 384], 0.f) * ap;
            else if (j < 416)  g_R[(size_t)p * LDIM + 192 + (j - 400)] = fmaxf(v + bpj[j - 400], 0.f);
            else               g_d[p] = v + bd0;
        }
    }
}

// ---------------- batched S0 = L * R^T (f32x2) ----------------
__global__ __launch_bounds__(256) void qk_gemm_kernel(float* __restrict__ S) {
    __shared__ float Ls[16][128];
    __shared__ float Rs[16][128];
    int tid = threadIdx.x;
    int b = blockIdx.z;
    int m0 = blockIdx.x * 128;
    int n0 = blockIdx.y * 128;
    int tr = tid >> 4, tc = tid & 15;
    ull acc2[4][8];
#pragma unroll
    for (int i = 0; i < 4; i++)
#pragma unroll
        for (int j = 0; j < 8; j++) acc2[i][j] = 0ull;

    const float* Lb = g_L + (size_t)b * NPTS * LDIM;
    const float* Rb = g_R + (size_t)b * NPTS * LDIM;

    for (int kc = 0; kc < LDIM; kc += 16) {
#pragma unroll
        for (int it = 0; it < 2; ++it) {
            int id = tid + it * 256;
            int row = id >> 2, q = id & 3;
            float4 u = *(const float4*)&Lb[(size_t)(n0 + row) * LDIM + kc + q * 4];
            Ls[q * 4 + 0][row] = u.x; Ls[q * 4 + 1][row] = u.y;
            Ls[q * 4 + 2][row] = u.z; Ls[q * 4 + 3][row] = u.w;
            float4 v = *(const float4*)&Rb[(size_t)(m0 + row) * LDIM + kc + q * 4];
            Rs[q * 4 + 0][row] = v.x; Rs[q * 4 + 1][row] = v.y;
            Rs[q * 4 + 2][row] = v.z; Rs[q * 4 + 3][row] = v.w;
        }
        __syncthreads();
#pragma unroll
        for (int k = 0; k < 16; ++k) {
            float4 a0 = *(const float4*)&Ls[k][tr * 8];
            float4 a1 = *(const float4*)&Ls[k][tr * 8 + 4];
            ull a2[4] = {pack2(a0.x, a0.y), pack2(a0.z, a0.w),
                         pack2(a1.x, a1.y), pack2(a1.z, a1.w)};
            float4 b0 = *(const float4*)&Rs[k][tc * 8];
            float4 b1 = *(const float4*)&Rs[k][tc * 8 + 4];
            ull bd2[8] = {pack2(b0.x, b0.x), pack2(b0.y, b0.y),
                          pack2(b0.z, b0.z), pack2(b0.w, b0.w),
                          pack2(b1.x, b1.x), pack2(b1.y, b1.y),
                          pack2(b1.z, b1.z), pack2(b1.w, b1.w)};
#pragma unroll
            for (int i = 0; i < 4; i++)
#pragma unroll
                for (int j = 0; j < 8; j++)
                    acc2[i][j] = fma2(a2[i], bd2[j], acc2[i][j]);
        }
        __syncthreads();
    }
#pragma unroll
    for (int i = 0; i < 4; i++) {
        float lo[8], hi[8];
#pragma unroll
        for (int j = 0; j < 8; j++) unpack2(acc2[i][j], lo[j], hi[j]);
        size_t off0 = ((size_t)b * NPTS + n0 + tr * 8 + 2 * i) * NPTS + m0 + tc * 8;
        size_t off1 = off0 + NPTS;
        *(float4*)&S[off0]     = make_float4(lo[0], lo[1], lo[2], lo[3]);
        *(float4*)&S[off0 + 4] = make_float4(lo[4], lo[5], lo[6], lo[7]);
        *(float4*)&S[off1]     = make_float4(hi[0], hi[1], hi[2], hi[3]);
        *(float4*)&S[off1 + 4] = make_float4(hi[4], hi[5], hi[6], hi[7]);
    }
}

// ---------------- per-pair geometry/angle MLP epilogue (f32x2) ----------------
__global__ __launch_bounds__(256) void pair_kernel(
    float* __restrict__ S, const float* __restrict__ xy,
    const float* __restrict__ Wg1, const float* __restrict__ bg1,
    const float* __restrict__ Wg2, const float* __restrict__ bg2,
    const float* __restrict__ alpha_geom,
    const float* __restrict__ Wa1, const float* __restrict__ ba1,
    const float* __restrict__ Wa2, const float* __restrict__ ba2,
    const float* __restrict__ alpha_angle,
    const float* __restrict__ logit_scale) {
    __shared__ ull sWg1d[12 * 32];   // duplicated f32x2 weights
    __shared__ ull sbg1d[32];
    __shared__ float sWg2[32];
    __shared__ ull sWa1d[6 * 16];
    __shared__ ull sba1d[16];
    __shared__ float sWa2[16];
    __shared__ float sxn[32], syn[32], sxm[32], sym[32], sdn[32];

    int tid = threadIdx.x;
    int b = blockIdx.z;
    int m0 = blockIdx.x * 32;
    int n0 = blockIdx.y * 32;

    for (int i = tid; i < 384; i += 256) { float w = Wg1[i]; sWg1d[i] = pack2(w, w); }
    if (tid < 96) { float w = Wa1[tid]; sWa1d[tid] = pack2(w, w); }
    if (tid >= 96 && tid < 128) {
        int i = tid - 96;
        float w = bg1[i]; sbg1d[i] = pack2(w, w);
        sWg2[i] = Wg2[i];
    }
    if (tid >= 128 && tid < 144) {
        int i = tid - 128;
        float w = ba1[i]; sba1d[i] = pack2(w, w);
        sWa2[i] = Wa2[i];
    }
    if (tid >= 160 && tid < 192) {
        int i = tid - 160;
        float2 pn = *(const float2*)&xy[((size_t)b * NPTS + n0 + i) * 2];
        syn[i] = pn.x; sxn[i] = pn.y;   // xy[...,0] = yv, xy[...,1] = xv
        float2 pm = *(const float2*)&xy[((size_t)b * NPTS + m0 + i) * 2];
        sym[i] = pm.x; sxm[i] = pm.y;
        sdn[i] = g_d[b * NPTS + n0 + i];
    }
    __syncthreads();

    int ty = tid >> 3;      // 0..31 : n within tile
    int tx = tid & 7;       // 0..7  : group of 4 m
    int n = n0 + ty;
    int mbase = m0 + tx * 4;

    float c0 = g_rot[2 * b], s0 = g_rot[2 * b + 1];
    float yn = syn[ty], xn = sxn[ty];

    const float sp = 1.41421356237f / 7.0f;                 // rbf spacing
    const float gam = 1.0f / (2.0f * sp * sp + 1e-8f);

    ull f2[2][12];
    float c1s[4], s1s[4];
#pragma unroll
    for (int pp = 0; pp < 2; ++pp) {
        float t[2][12];
#pragma unroll
        for (int q = 0; q < 2; ++q) {
            int p = pp * 2 + q;
            float ym = sym[tx * 4 + p], xm = sxm[tx * 4 + p];
            float dy = yn - ym, dx = xn - xm;
            float r2 = dy * dy + dx * dx;
            float r = sqrtf(r2 + 1e-8f);
            float inv = rsqrtf(r2);
            float ct, st;
            if (r2 == 0.f) { ct = 1.f; st = 0.f; }
            else { ct = dx * inv; st = dy * inv; }
            float c1 = ct * c0 + st * s0;   // cos(theta - theta0)
            float s1 = st * c0 - ct * s0;   // sin(theta - theta0)
            c1s[p] = c1; s1s[p] = s1;
            t[q][0] = dy; t[q][1] = dx;
#pragma unroll
            for (int k = 0; k < 8; ++k) {
                float dmu = r - (float)k * sp;
                t[q][2 + k] = __expf(-gam * dmu * dmu);
            }
            t[q][10] = c1; t[q][11] = s1;
        }
#pragma unroll
        for (int i = 0; i < 12; ++i) f2[pp][i] = pack2(t[0][i], t[1][i]);
    }

    float bg2v = bg2[0], ba2v = ba2[0];
    float accG[4] = {bg2v, bg2v, bg2v, bg2v};
    float accA[4] = {ba2v, ba2v, ba2v, ba2v};

#pragma unroll 4
    for (int j = 0; j < 32; ++j) {
        ull bj = sbg1d[j];
        ull h0 = bj, h1 = bj;
#pragma unroll
        for (int i = 0; i < 12; ++i) {
            ull w = sWg1d[i * 32 + j];
            h0 = fma2(f2[0][i], w, h0);
            h1 = fma2(f2[1][i], w, h1);
        }
        float a0, a1, a2, a3;
        unpack2(h0, a0, a1); unpack2(h1, a2, a3);
        float w2 = sWg2[j];
        accG[0] = fmaf(fmaxf(a0, 0.f), w2, accG[0]);
        accG[1] = fmaf(fmaxf(a1, 0.f), w2, accG[1]);
        accG[2] = fmaf(fmaxf(a2, 0.f), w2, accG[2]);
        accG[3] = fmaf(fmaxf(a3, 0.f), w2, accG[3]);
    }

    // angle features (packed)
    ull fa2[2][6];
#pragma unroll
    for (int pp = 0; pp < 2; ++pp) {
        float t[2][6];
#pragma unroll
        for (int q = 0; q < 2; ++q) {
            int p = pp * 2 + q;
            float c1 = c1s[p], s1 = s1s[p];
            float c2 = c1 * c1 - s1 * s1;
            float s2 = 2.f * c1 * s1;
            float c4 = c2 * c2 - s2 * s2;
            float s4 = 2.f * c2 * s2;
            t[q][0] = c1; t[q][1] = s1; t[q][2] = c2;
            t[q][3] = s2; t[q][4] = c4; t[q][5] = s4;
        }
#pragma unroll
        for (int i = 0; i < 6; ++i) fa2[pp][i] = pack2(t[0][i], t[1][i]);
    }

#pragma unroll 4
    for (int j = 0; j < 16; ++j) {
        ull bj = sba1d[j];
        ull h0 = bj, h1 = bj;
#pragma unroll
        for (int i = 0; i < 6; ++i) {
            ull w = sWa1d[i * 16 + j];
            h0 = fma2(fa2[0][i], w, h0);
            h1 = fma2(fa2[1][i], w, h1);
        }
        float a0, a1, a2, a3;
        unpack2(h0, a0, a1); unpack2(h1, a2, a3);
        float w2 = sWa2[j];
        accA[0] = fmaf(fmaxf(a0, 0.f), w2, accA[0]);
        accA[1] = fmaf(fmaxf(a1, 0.f), w2, accA[1]);
        accA[2] = fmaf(fmaxf(a2, 0.f), w2, accA[2]);
        accA[3] = fmaf(fmaxf(a3, 0.f), w2, accA[3]);
    }

    float ag = fmaxf(alpha_geom[0], 0.f);
    float aa = fmaxf(alpha_angle[0], 0.f);
    float ls = fmaxf(logit_scale[0], 0.01f);

    size_t off = ((size_t)b * NPTS + n) * NPTS + mbase;
    float4 s4v = *(const float4*)&S[off];
    float sv[4] = {s4v.x, s4v.y, s4v.z, s4v.w};
#pragma unroll
    for (int p = 0; p < 4; ++p) {
        float v = sv[p] + ag * accG[p] + aa * accA[p];
        if (n == mbase + p) v += sdn[ty];
        sv[p] = v * ls;
    }
    *(float4*)&S[off] = make_float4(sv[0], sv[1], sv[2], sv[3]);
}

// ---------------- launch ----------------
extern "C" void kernel_launch(void* const* d_in, const int* in_sizes, int n_in,
                              void* d_out, int out_size) {
    const float* feats       = (const float*)d_in[0];
    const float* xy          = (const float*)d_in[1];
    const float* Wq          = (const float*)d_in[2];
    const float* Wk          = (const float*)d_in[3];
    const float* Wpi         = (const float*)d_in[4];
    const float* bpi         = (const float*)d_in[5];
    const float* Wpj         = (const float*)d_in[6];
    const float* bpj         = (const float*)d_in[7];
    const float* alpha_pair  = (const float*)d_in[8];
    const float* Wg1         = (const float*)d_in[9];
    const float* bg1         = (const float*)d_in[10];
    const float* Wg2         = (const float*)d_in[11];
    const float* bg2         = (const float*)d_in[12];
    const float* alpha_geom  = (const float*)d_in[13];
    const float* Wa1         = (const float*)d_in[14];
    const float* ba1         = (const float*)d_in[15];
    const float* Wa2         = (const float*)d_in[16];
    const float* ba2         = (const float*)d_in[17];
    const float* alpha_angle = (const float*)d_in[18];
    const float* Wd          = (const float*)d_in[19];
    const float* bd          = (const float*)d_in[20];
    const float* logit_scale = (const float*)d_in[21];
    float* S = (float*)d_out;

    theta0_kernel<<<1, 256>>>(xy);
    pack_w_kernel<<<(CDIM * WCOLS + 255) / 256, 256>>>(Wq, Wk, Wpi, Wpj, Wd);
    proj_gemm_kernel<<<dim3(7, 32), 256>>>(feats, bpi, bpj, alpha_pair, bd);
    qk_gemm_kernel<<<dim3(4, 4, 8), 256>>>(S);
    pair_kernel<<<dim3(16, 16, 8), 256>>>(S, xy, Wg1, bg1, Wg2, bg2, alpha_geom,
                                          Wa1, ba1, Wa2, ba2, alpha_angle,
                                          logit_scale);
}

// round 8
// speedup vs baseline: 1.1109x; 1.0052x over previous
#include <cuda_runtime.h>

#define NPTS 512
#define CDIM 384
#define LDIM 208   // 192 QK + 16 pair
#define NB 8
#define WCOLS 417  // packed projection columns

typedef unsigned long long ull;

// ---------------- device scratch ----------------
__device__ float g_L[NB * NPTS * LDIM];  // [Q*HEAD_SCALE | ap*relu(x@Wpi+bpi)]
__device__ float g_R[NB * NPTS * LDIM];  // [K            | relu(x@Wpj+bpj)   ]
__device__ float g_d[NB * NPTS];         // x@Wd + bd
__device__ float g_rot[2 * NB];          // (cos t0, sin t0) per batch
__device__ float g_W[CDIM * WCOLS];      // packed [Wq|Wk|Wpi|Wpj|Wd]

// ---------------- f32x2 helpers ----------------
__device__ __forceinline__ ull pack2(float lo, float hi) {
    ull r; asm("mov.b64 %0,{%1,%2};" : "=l"(r) : "f"(lo), "f"(hi)); return r;
}
__device__ __forceinline__ void unpack2(ull v, float& lo, float& hi) {
    asm("mov.b64 {%0,%1},%2;" : "=f"(lo), "=f"(hi) : "l"(v));
}
__device__ __forceinline__ ull fma2(ull a, ull b, ull c) {
    ull d; asm("fma.rn.f32x2 %0,%1,%2,%3;" : "=l"(d) : "l"(a), "l"(b), "l"(c)); return d;
}

// ---------------- threefry / jax normal ----------------
__device__ __forceinline__ unsigned rotl32(unsigned v, int s) {
    return (v << s) | (v >> (32 - s));
}

__device__ void threefry2x32(unsigned k0, unsigned k1, unsigned c0, unsigned c1,
                             unsigned& o0, unsigned& o1) {
    unsigned k2 = k0 ^ k1 ^ 0x1BD11BDAu;
    unsigned x0 = c0 + k0, x1 = c1 + k1;
#define TF_R(r) { x0 += x1; x1 = rotl32(x1, r); x1 ^= x0; }
    TF_R(13) TF_R(15) TF_R(26) TF_R(6)   x0 += k1; x1 += k2 + 1u;
    TF_R(17) TF_R(29) TF_R(16) TF_R(24)  x0 += k2; x1 += k0 + 2u;
    TF_R(13) TF_R(15) TF_R(26) TF_R(6)   x0 += k0; x1 += k1 + 3u;
    TF_R(17) TF_R(29) TF_R(16) TF_R(24)  x0 += k1; x1 += k2 + 4u;
    TF_R(13) TF_R(15) TF_R(26) TF_R(6)   x0 += k2; x1 += k0 + 5u;
#undef TF_R
    o0 = x0; o1 = x1;
}

__device__ unsigned jax_random_bits_partitionable(unsigned i) {
    unsigned o0, o1;
    threefry2x32(0u, 42u, 0u, i, o0, o1);
    return o0 ^ o1;
}

__device__ float erfinv_f(float x) {
    float w = -log1pf(-x * x);
    float p;
    if (w < 5.0f) {
        w -= 2.5f;
        p = 2.81022636e-08f;
        p = fmaf(p, w, 3.43273939e-07f);
        p = fmaf(p, w, -3.5233877e-06f);
        p = fmaf(p, w, -4.39150654e-06f);
        p = fmaf(p, w, 0.00021858087f);
        p = fmaf(p, w, -0.00125372503f);
        p = fmaf(p, w, -0.00417768164f);
        p = fmaf(p, w, 0.246640727f);
        p = fmaf(p, w, 1.50140941f);
    } else {
        w = sqrtf(w) - 3.0f;
        p = -0.000200214257f;
        p = fmaf(p, w, 0.000100950558f);
        p = fmaf(p, w, 0.00134934322f);
        p = fmaf(p, w, -0.00367342844f);
        p = fmaf(p, w, 0.00573950773f);
        p = fmaf(p, w, -0.0076224613f);
        p = fmaf(p, w, 0.00943887047f);
        p = fmaf(p, w, 1.00167406f);
        p = fmaf(p, w, 2.83297682f);
    }
    return p * x;
}

__device__ float jax_normal_from_bits(unsigned bits) {
    float f = __uint_as_float((bits >> 9) | 0x3f800000u) - 1.0f;  // [0,1)
    float lo = __uint_as_float(0xBF7FFFFFu);                      // nextafter(-1,0)
    float span = 1.0f - lo;
    float val = f * span + lo;
    val = fmaxf(lo, val);
    return 1.41421356237f * erfinv_f(val);
}

// ---------------- theta0: covariance + power iteration ----------------
__global__ void theta0_kernel(const float* __restrict__ xy) {
    int w = threadIdx.x >> 5, lane = threadIdx.x & 31;
    const float* p = xy + (size_t)w * NPTS * 2;
    float sx = 0.f, sy = 0.f;
    for (int i = lane; i < NPTS; i += 32) { sx += p[2 * i]; sy += p[2 * i + 1]; }
    for (int o = 16; o; o >>= 1) {
        sx += __shfl_xor_sync(~0u, sx, o);
        sy += __shfl_xor_sync(~0u, sy, o);
    }
    float mx = sx / (float)NPTS, my = sy / (float)NPTS;
    float cxx = 0.f, cxy = 0.f, cyy = 0.f;
    for (int i = lane; i < NPTS; i += 32) {
        float a = p[2 * i] - mx, b = p[2 * i + 1] - my;
        cxx += a * a; cxy += a * b; cyy += b * b;
    }
    for (int o = 16; o; o >>= 1) {
        cxx += __shfl_xor_sync(~0u, cxx, o);
        cxy += __shfl_xor_sync(~0u, cxy, o);
        cyy += __shfl_xor_sync(~0u, cyy, o);
    }
    if (lane == 0) {
        float denom = (float)NPTS + 1e-8f;
        cxx /= denom; cxy /= denom; cyy /= denom;
        unsigned n0bits = jax_random_bits_partitionable(2u * (unsigned)w);
        unsigned n1bits = jax_random_bits_partitionable(2u * (unsigned)w + 1u);
        float v0 = jax_normal_from_bits(n0bits);
        float v1 = jax_normal_from_bits(n1bits);
        float nrm = sqrtf(v0 * v0 + v1 * v1);
        v0 /= (nrm + 1e-8f); v1 /= (nrm + 1e-8f);
#pragma unroll
        for (int it = 0; it < 5; ++it) {
            float w0 = cxx * v0 + cxy * v1;
            float w1 = cxy * v0 + cyy * v1;
            nrm = sqrtf(w0 * w0 + w1 * w1);
            v0 = w0 / (nrm + 1e-8f);
            v1 = w1 / (nrm + 1e-8f);
        }
        g_rot[2 * w] = v0;      // cos theta0
        g_rot[2 * w + 1] = v1;  // sin theta0
    }
}

// ---------------- pack projection weights into one matrix ----------------
__global__ void pack_w_kernel(const float* __restrict__ Wq, const float* __restrict__ Wk,
                              const float* __restrict__ Wpi, const float* __restrict__ Wpj,
                              const float* __restrict__ Wd) {
    int idx = blockIdx.x * 256 + threadIdx.x;
    if (idx >= CDIM * WCOLS) return;
    int k = idx / WCOLS, j = idx - k * WCOLS;
    float w;
    if (j < 192)       w = Wq[k * 192 + j];
    else if (j < 384)  w = Wk[k * 192 + j - 192];
    else if (j < 400)  w = Wpi[k * 16 + j - 384];
    else if (j < 416)  w = Wpj[k * 16 + j - 400];
    else               w = Wd[k];
    g_W[idx] = w;
}

// ---------------- fused fold + projection GEMM (f32x2, 64x64 tiles) ----------------
__global__ __launch_bounds__(256) void proj_gemm_kernel(
    const float* __restrict__ feats,
    const float* __restrict__ bpi, const float* __restrict__ bpj,
    const float* __restrict__ alpha_pair, const float* __restrict__ bd) {
    __shared__ float As[16][64];
    __shared__ float Bs[16][64];
    int tid = threadIdx.x;
    int n0 = blockIdx.x * 64;   // col tile
    int m0 = blockIdx.y * 64;   // row tile (points)
    int tr = tid >> 4, tc = tid & 15;
    ull acc2[2][4];
#pragma unroll
    for (int i = 0; i < 2; i++)
#pragma unroll
        for (int j = 0; j < 4; j++) acc2[i][j] = 0ull;

    for (int kc = 0; kc < CDIM; kc += 16) {
        {
            int row = tid >> 2, q = tid & 3;
            int pidx = m0 + row;
            int b = pidx >> 9, n = pidx & 511;
            const float* base = feats + ((size_t)b * (2 * NPTS + 1) + 1 + 2 * n) * CDIM + kc + q * 4;
            float4 u = *(const float4*)base;
            float4 v = *(const float4*)(base + CDIM);
            As[q * 4 + 0][row] = 0.5f * (u.x + v.x);
            As[q * 4 + 1][row] = 0.5f * (u.y + v.y);
            As[q * 4 + 2][row] = 0.5f * (u.z + v.z);
            As[q * 4 + 3][row] = 0.5f * (u.w + v.w);
        }
#pragma unroll
        for (int it = 0; it < 4; ++it) {
            int id = tid + it * 256;
            int k = id >> 6, n = id & 63;
            int j = n0 + n;
            Bs[k][n] = (j < WCOLS) ? g_W[(size_t)(kc + k) * WCOLS + j] : 0.f;
        }
        __syncthreads();
#pragma unroll
        for (int k = 0; k < 16; ++k) {
            float4 a = *(const float4*)&As[k][tr * 4];
            ull a2[2] = {pack2(a.x, a.y), pack2(a.z, a.w)};
            float4 b4 = *(const float4*)&Bs[k][tc * 4];
            ull bd2[4] = {pack2(b4.x, b4.x), pack2(b4.y, b4.y),
                          pack2(b4.z, b4.z), pack2(b4.w, b4.w)};
#pragma unroll
            for (int i = 0; i < 2; i++)
#pragma unroll
                for (int j = 0; j < 4; j++)
                    acc2[i][j] = fma2(a2[i], bd2[j], acc2[i][j]);
        }
        __syncthreads();
    }

    float acc[4][4];
#pragma unroll
    for (int i = 0; i < 2; i++)
#pragma unroll
        for (int j = 0; j < 4; j++)
            unpack2(acc2[i][j], acc[2 * i][j], acc[2 * i + 1][j]);

    float ap = fmaxf(alpha_pair[0], 0.f);
    float bd0 = bd[0];
    const float HS = 0.17677669529663687f;  // 1/sqrt(32)
#pragma unroll
    for (int jj = 0; jj < 4; ++jj) {
        int j = n0 + tc * 4 + jj;
        if (j > 416) continue;
#pragma unroll
        for (int ii = 0; ii < 4; ++ii) {
            int p = m0 + tr * 4 + ii;
            float v = acc[ii][jj];
            if (j < 192)       g_L[(size_t)p * LDIM + j] = v * HS;
            else if (j < 384)  g_R[(size_t)p * LDIM + (j - 192)] = v;
            else if (j < 400)  g_L[(size_t)p * LDIM + 192 + (j - 384)] = fmaxf(v + bpi[j - 384], 0.f) * ap;
            else if (j < 416)  g_R[(size_t)p * LDIM + 192 + (j - 400)] = fmaxf(v + bpj[j - 400], 0.f);
            else               g_d[p] = v + bd0;
        }
    }
}

// ---------------- batched S0 = L * R^T (f32x2, 64x64 tiles) ----------------
__global__ __launch_bounds__(256) void qk_gemm_kernel(float* __restrict__ S) {
    __shared__ float Ls[16][64];
    __shared__ float Rs[16][64];
    int tid = threadIdx.x;
    int b = blockIdx.z;
    int m0 = blockIdx.x * 64;
    int n0 = blockIdx.y * 64;
    int tr = tid >> 4, tc = tid & 15;
    ull acc2[2][4];
#pragma unroll
    for (int i = 0; i < 2; i++)
#pragma unroll
        for (int j = 0; j < 4; j++) acc2[i][j] = 0ull;

    const float* Lb = g_L + (size_t)b * NPTS * LDIM;
    const float* Rb = g_R + (size_t)b * NPTS * LDIM;

    for (int kc = 0; kc < LDIM; kc += 16) {
        {
            int row = tid >> 2, q = tid & 3;
            float4 u = *(const float4*)&Lb[(size_t)(n0 + row) * LDIM + kc + q * 4];
            Ls[q * 4 + 0][row] = u.x; Ls[q * 4 + 1][row] = u.y;
            Ls[q * 4 + 2][row] = u.z; Ls[q * 4 + 3][row] = u.w;
            float4 v = *(const float4*)&Rb[(size_t)(m0 + row) * LDIM + kc + q * 4];
            Rs[q * 4 + 0][row] = v.x; Rs[q * 4 + 1][row] = v.y;
            Rs[q * 4 + 2][row] = v.z; Rs[q * 4 + 3][row] = v.w;
        }
        __syncthreads();
#pragma unroll
        for (int k = 0; k < 16; ++k) {
            float4 a = *(const float4*)&Ls[k][tr * 4];
            ull a2[2] = {pack2(a.x, a.y), pack2(a.z, a.w)};
            float4 b4 = *(const float4*)&Rs[k][tc * 4];
            ull bd2[4] = {pack2(b4.x, b4.x), pack2(b4.y, b4.y),
                          pack2(b4.z, b4.z), pack2(b4.w, b4.w)};
#pragma unroll
            for (int i = 0; i < 2; i++)
#pragma unroll
                for (int j = 0; j < 4; j++)
                    acc2[i][j] = fma2(a2[i], bd2[j], acc2[i][j]);
        }
        __syncthreads();
    }
#pragma unroll
    for (int i = 0; i < 2; i++) {
        float lo[4], hi[4];
#pragma unroll
        for (int j = 0; j < 4; j++) unpack2(acc2[i][j], lo[j], hi[j]);
        size_t off0 = ((size_t)b * NPTS + n0 + tr * 4 + 2 * i) * NPTS + m0 + tc * 4;
        size_t off1 = off0 + NPTS;
        *(float4*)&S[off0] = make_float4(lo[0], lo[1], lo[2], lo[3]);
        *(float4*)&S[off1] = make_float4(hi[0], hi[1], hi[2], hi[3]);
    }
}

// ---------------- per-pair geometry/angle MLP epilogue (f32x2) ----------------
__global__ __launch_bounds__(256) void pair_kernel(
    float* __restrict__ S, const float* __restrict__ xy,
    const float* __restrict__ Wg1, const float* __restrict__ bg1,
    const float* __restrict__ Wg2, const float* __restrict__ bg2,
    const float* __restrict__ alpha_geom,
    const float* __restrict__ Wa1, const float* __restrict__ ba1,
    const float* __restrict__ Wa2, const float* __restrict__ ba2,
    const float* __restrict__ alpha_angle,
    const float* __restrict__ logit_scale) {
    __shared__ ull sWg1d[12 * 32];   // duplicated f32x2 weights
    __shared__ ull sbg1d[32];
    __shared__ float sWg2[32];
    __shared__ ull sWa1d[6 * 16];
    __shared__ ull sba1d[16];
    __shared__ float sWa2[16];
    __shared__ float sxn[32], syn[32], sxm[32], sym[32], sdn[32];

    int tid = threadIdx.x;
    int b = blockIdx.z;
    int m0 = blockIdx.x * 32;
    int n0 = blockIdx.y * 32;

    for (int i = tid; i < 384; i += 256) { float w = Wg1[i]; sWg1d[i] = pack2(w, w); }
    if (tid < 96) { float w = Wa1[tid]; sWa1d[tid] = pack2(w, w); }
    if (tid >= 96 && tid < 128) {
        int i = tid - 96;
        float w = bg1[i]; sbg1d[i] = pack2(w, w);
        sWg2[i] = Wg2[i];
    }
    if (tid >= 128 && tid < 144) {
        int i = tid - 128;
        float w = ba1[i]; sba1d[i] = pack2(w, w);
        sWa2[i] = Wa2[i];
    }
    if (tid >= 160 && tid < 192) {
        int i = tid - 160;
        float2 pn = *(const float2*)&xy[((size_t)b * NPTS + n0 + i) * 2];
        syn[i] = pn.x; sxn[i] = pn.y;   // xy[...,0] = yv, xy[...,1] = xv
        float2 pm = *(const float2*)&xy[((size_t)b * NPTS + m0 + i) * 2];
        sym[i] = pm.x; sxm[i] = pm.y;
        sdn[i] = g_d[b * NPTS + n0 + i];
    }
    __syncthreads();

    int ty = tid >> 3;      // 0..31 : n within tile
    int tx = tid & 7;       // 0..7  : group of 4 m
    int n = n0 + ty;
    int mbase = m0 + tx * 4;

    float c0 = g_rot[2 * b], s0 = g_rot[2 * b + 1];
    float yn = syn[ty], xn = sxn[ty];

    const float sp = 1.41421356237f / 7.0f;                 // rbf spacing
    const float gam = 1.0f / (2.0f * sp * sp + 1e-8f);
    const float C2 = 2.0f * gam * sp;
    // cst[k] = exp(-gam*(k*sp)^2) = exp(-k^2/2) (up to 1e-9)
    const float cst1 = 0.60653065971f;
    const float cst2 = 0.13533528324f;
    const float cst3 = 0.011108996538f;
    const float cst4 = 3.3546262790e-4f;
    const float cst5 = 3.7266531720e-6f;
    const float cst6 = 1.5229979745e-8f;
    const float cst7 = 2.2897348457e-11f;

    ull f2[2][12];
    float c1s[4], s1s[4];
#pragma unroll
    for (int pp = 0; pp < 2; ++pp) {
        float t[2][12];
#pragma unroll
        for (int q = 0; q < 2; ++q) {
            int p = pp * 2 + q;
            float ym = sym[tx * 4 + p], xm = sxm[tx * 4 + p];
            float dy = yn - ym, dx = xn - xm;
            float r2 = dy * dy + dx * dx;
            float fr2 = r2 + 1e-8f;
            float r = sqrtf(fr2);
            float inv = rsqrtf(r2);
            float ct, st;
            if (r2 == 0.f) { ct = 1.f; st = 0.f; }
            else { ct = dx * inv; st = dy * inv; }
            float c1 = ct * c0 + st * s0;   // cos(theta - theta0)
            float s1 = st * c0 - ct * s0;   // sin(theta - theta0)
            c1s[p] = c1; s1s[p] = s1;
            t[q][0] = dy; t[q][1] = dx;
            // phi_k = e0 * Cr^k * cst_k
            float e0 = __expf(-gam * fr2);
            float Cr = __expf(C2 * r);
            t[q][2] = e0;
            float tt = e0;
            tt *= Cr; t[q][3] = tt * cst1;
            tt *= Cr; t[q][4] = tt * cst2;
            tt *= Cr; t[q][5] = tt * cst3;
            tt *= Cr; t[q][6] = tt * cst4;
            tt *= Cr; t[q][7] = tt * cst5;
            tt *= Cr; t[q][8] = tt * cst6;
            tt *= Cr; t[q][9] = tt * cst7;
            t[q][10] = c1; t[q][11] = s1;
        }
#pragma unroll
        for (int i = 0; i < 12; ++i) f2[pp][i] = pack2(t[0][i], t[1][i]);
    }

    float bg2v = bg2[0], ba2v = ba2[0];
    float accG[4] = {bg2v, bg2v, bg2v, bg2v};
    float accA[4] = {ba2v, ba2v, ba2v, ba2v};

#pragma unroll 4
    for (int j = 0; j < 32; ++j) {
        ull bj = sbg1d[j];
        ull h0 = bj, h1 = bj;
#pragma unroll
        for (int i = 0; i < 12; ++i) {
            ull w = sWg1d[i * 32 + j];
            h0 = fma2(f2[0][i], w, h0);
            h1 = fma2(f2[1][i], w, h1);
        }
        float a0, a1, a2, a3;
        unpack2(h0, a0, a1); unpack2(h1, a2, a3);
        float w2 = sWg2[j];
        accG[0] = fmaf(fmaxf(a0, 0.f), w2, accG[0]);
        accG[1] = fmaf(fmaxf(a1, 0.f), w2, accG[1]);
        accG[2] = fmaf(fmaxf(a2, 0.f), w2, accG[2]);
        accG[3] = fmaf(fmaxf(a3, 0.f), w2, accG[3]);
    }

    // angle features (packed)
    ull fa2[2][6];
#pragma unroll
    for (int pp = 0; pp < 2; ++pp) {
        float t[2][6];
#pragma unroll
        for (int q = 0; q < 2; ++q) {
            int p = pp * 2 + q;
            float c1 = c1s[p], s1 = s1s[p];
            float c2 = c1 * c1 - s1 * s1;
            float s2 = 2.f * c1 * s1;
            float c4 = c2 * c2 - s2 * s2;
            float s4 = 2.f * c2 * s2;
            t[q][0] = c1; t[q][1] = s1; t[q][2] = c2;
            t[q][3] = s2; t[q][4] = c4; t[q][5] = s4;
        }
#pragma unroll
        for (int i = 0; i < 6; ++i) fa2[pp][i] = pack2(t[0][i], t[1][i]);
    }

#pragma unroll 4
    for (int j = 0; j < 16; ++j) {
        ull bj = sba1d[j];
        ull h0 = bj, h1 = bj;
#pragma unroll
        for (int i = 0; i < 6; ++i) {
            ull w = sWa1d[i * 16 + j];
            h0 = fma2(fa2[0][i], w, h0);
            h1 = fma2(fa2[1][i], w, h1);
        }
        float a0, a1, a2, a3;
        unpack2(h0, a0, a1); unpack2(h1, a2, a3);
        float w2 = sWa2[j];
        accA[0] = fmaf(fmaxf(a0, 0.f), w2, accA[0]);
        accA[1] = fmaf(fmaxf(a1, 0.f), w2, accA[1]);
        accA[2] = fmaf(fmaxf(a2, 0.f), w2, accA[2]);
        accA[3] = fmaf(fmaxf(a3, 0.f), w2, accA[3]);
    }

    float ag = fmaxf(alpha_geom[0], 0.f);
    float aa = fmaxf(alpha_angle[0], 0.f);
    float ls = fmaxf(logit_scale[0], 0.01f);

    size_t off = ((size_t)b * NPTS + n) * NPTS + mbase;
    float4 s4v = *(const float4*)&S[off];
    float sv[4] = {s4v.x, s4v.y, s4v.z, s4v.w};
#pragma unroll
    for (int p = 0; p < 4; ++p) {
        float v = sv[p] + ag * accG[p] + aa * accA[p];
        if (n == mbase + p) v += sdn[ty];
        sv[p] = v * ls;
    }
    *(float4*)&S[off] = make_float4(sv[0], sv[1], sv[2], sv[3]);
}

// ---------------- launch ----------------
extern "C" void kernel_launch(void* const* d_in, const int* in_sizes, int n_in,
                              void* d_out, int out_size) {
    const float* feats       = (const float*)d_in[0];
    const float* xy          = (const float*)d_in[1];
    const float* Wq          = (const float*)d_in[2];
    const float* Wk          = (const float*)d_in[3];
    const float* Wpi         = (const float*)d_in[4];
    const float* bpi         = (const float*)d_in[5];
    const float* Wpj         = (const float*)d_in[6];
    const float* bpj         = (const float*)d_in[7];
    const float* alpha_pair  = (const float*)d_in[8];
    const float* Wg1         = (const float*)d_in[9];
    const float* bg1         = (const float*)d_in[10];
    const float* Wg2         = (const float*)d_in[11];
    const float* bg2         = (const float*)d_in[12];
    const float* alpha_geom  = (const float*)d_in[13];
    const float* Wa1         = (const float*)d_in[14];
    const float* ba1         = (const float*)d_in[15];
    const float* Wa2         = (const float*)d_in[16];
    const float* ba2         = (const float*)d_in[17];
    const float* alpha_angle = (const float*)d_in[18];
    const float* Wd          = (const float*)d_in[19];
    const float* bd          = (const float*)d_in[20];
    const float* logit_scale = (const float*)d_in[21];
    float* S = (float*)d_out;

    theta0_kernel<<<1, 256>>>(xy);
    pack_w_kernel<<<(CDIM * WCOLS + 255) / 256, 256>>>(Wq, Wk, Wpi, Wpj, Wd);
    proj_gemm_kernel<<<dim3(7, 64), 256>>>(feats, bpi, bpj, alpha_pair, bd);
    qk_gemm_kernel<<<dim3(8, 8, 8), 256>>>(S);
    pair_kernel<<<dim3(16, 16, 8), 256>>>(S, xy, Wg1, bg1, Wg2, bg2, alpha_geom,
                                          Wa1, ba1, Wa2, ba2, alpha_angle,
                                          logit_scale);
}